// round 6
// baseline (speedup 1.0000x reference)
#include <cuda_runtime.h>
#include <cuda_bf16.h>

// Problem constants
#define B_  8
#define C_  256
#define K_  21
#define KP  24            // K padded to 12 f32x2 pairs
#define HL  64
#define PL  (HL*HL)       // 4096 low-res pixels
#define HH  512
#define PH  (HH*HH)       // 262144 hi-res pixels
#define NBLK 32           // q-partial blocks per batch
#define NT  20            // taps per low-res bin (padded with zeros)
#define RUP (511.0f/63.0f)
#define SDN (63.0f/511.0f)

// Scratch (device globals)
__device__ float g_tmpx[B_ * 3 * HH * HL];       // X-pass adjoint (3 MB)
__device__ float g_part[B_ * NBLK * K_ * 3];     // q block partials

// packed f32x2 helpers
#define FMA2(acc, v2, w2) \
    asm("fma.rn.f32x2 %0, %1, %2, %0;" : "+l"(acc) : "l"(v2), "l"(w2))
__device__ __forceinline__ unsigned long long pack2(float lo, float hi) {
    unsigned long long r;
    asm("mov.b64 %0, {%1, %2};" : "=l"(r) : "r"(__float_as_uint(lo)), "r"(__float_as_uint(hi)));
    return r;
}
__device__ __forceinline__ void unpack2(unsigned long long v, float& lo, float& hi) {
    unsigned int a, b;
    asm("mov.b64 {%0, %1}, %2;" : "=r"(a), "=r"(b) : "l"(v));
    lo = __uint_as_float(a); hi = __uint_as_float(b);
}

// Adjoint tap weight: contribution of hires coord X to lowres bin l (one axis).
__device__ __forceinline__ float tap_w(int X, int l) {
    if (X > HH - 1) return 0.0f;
    float xs = (float)X * SDN;
    int   x0 = (int)xs;
    float wx = xs - (float)x0;
    int   x1 = min(x0 + 1, HL - 1);
    return (x0 == l ? (1.0f - wx) : 0.0f) + (x1 == l ? wx : 0.0f);
}
// First tap index for bin l, clamped so l's 20-tap window stays in [0, HH).
__device__ __forceinline__ int tap_base(int l) {
    int lo = max(0, (int)floorf((l - 1) * RUP));
    return min(lo, HH - NT);
}

// ---------------------------------------------------------------------------
// Kernel 1: adjoint of bilinear upsample, X direction, table-driven.
// One 256-thread block handles 4 hires rows; rows staged in smem.
// ---------------------------------------------------------------------------
__global__ __launch_bounds__(256) void k_adj_x(const float* __restrict__ x)
{
    __shared__ float srow[4][HH];
    __shared__ float swt[HL][NT];     // 5.1 KB
    __shared__ int   sbase[HL];

    int tid    = threadIdx.x;
    int sub    = tid >> 6;
    int lane64 = tid & 63;
    int rowid  = blockIdx.x * 4 + sub;         // (b*3+c)*HH + Y

    // build tap table (threads 0..63), once per block
    if (tid < HL) {
        int xl = tid;
        int base = tap_base(xl);
        sbase[xl] = base;
#pragma unroll
        for (int j = 0; j < NT; j++) swt[xl][j] = tap_w(base + j, xl);
    }
    // coalesced row load: 64 threads x 2 float4 = 512 floats
    {
        float4*       s4 = (float4*)srow[sub];
        const float4* r4 = (const float4*)(x + (size_t)rowid * HH);
        s4[lane64]      = r4[lane64];
        s4[64 + lane64] = r4[64 + lane64];
    }
    __syncthreads();

    const int xl   = lane64;
    const int base = sbase[xl];
    const float* row = srow[sub] + base;
    float s = 0.f;
#pragma unroll
    for (int j = 0; j < NT; j++) s = fmaf(swt[xl][j], row[j], s);

    g_tmpx[(size_t)rowid * HL + xl] = s;
}

// ---------------------------------------------------------------------------
// Kernel 2 (fused): Y-adjoint (table-driven) + logits (f32x2 GEMM) + softmax
//                   + q block-partials.
// grid (32, 8), block 128, one thread per low-res pixel.
// ---------------------------------------------------------------------------
__global__ __launch_bounds__(128) void k_fused(
    const float* __restrict__ fm, const float* __restrict__ Wc,
    const float* __restrict__ bc)
{
    __shared__ ulonglong2 sWT2[C_][6];        // W^T padded: 24 floats/c (24.6 KB)
    __shared__ float      spart[4][K_ * 3];
    __shared__ float      sywt[2][NT];        // Y taps for this block's 2 yl rows

    int tid = threadIdx.x;
    int b   = blockIdx.y;
    int p   = blockIdx.x * 128 + tid;
    int xl  = p & (HL - 1);
    int yl  = p >> 6;
    int yl0 = (blockIdx.x * 128) >> 6;        // first yl in block

    // fill W^T (padded with zeros for k >= 21); float view of sWT2 is [C_][KP]
    {
        float* sWTf = (float*)sWT2;
        for (int i = tid; i < C_ * KP; i += 128) {
            int c = i / KP, k = i % KP;
            sWTf[i] = (k < K_) ? Wc[k * C_ + c] : 0.0f;
        }
    }
    // Y tap table for the 2 yl rows this block covers (threads 0..39)
    if (tid < 2 * NT) {
        int r = tid / NT, j = tid % NT;
        int l = yl0 + r;
        sywt[r][j] = tap_w(tap_base(l) + j, l);
    }
    __syncthreads();

    // --- Y-adjoint gather: xdown[c] for this pixel ---
    float xd0 = 0.f, xd1 = 0.f, xd2 = 0.f;
    {
        int base = tap_base(yl);
        const float* wrow = sywt[yl - yl0];
        const float* t0 = g_tmpx + ((size_t)(b * 3 + 0) * HH + base) * HL + xl;
        const float* t1 = g_tmpx + ((size_t)(b * 3 + 1) * HH + base) * HL + xl;
        const float* t2 = g_tmpx + ((size_t)(b * 3 + 2) * HH + base) * HL + xl;
#pragma unroll
        for (int j = 0; j < NT; j++) {
            float w = wrow[j];
            size_t o = (size_t)j * HL;
            xd0 = fmaf(w, t0[o], xd0);
            xd1 = fmaf(w, t1[o], xd1);
            xd2 = fmaf(w, t2[o], xd2);
        }
    }

    // --- logits GEMM, packed f32x2 over 12 k-pairs ---
    const float* fmb = fm + (size_t)b * C_ * PL + p;
    unsigned long long acc2[KP / 2];
#pragma unroll
    for (int j = 0; j < KP / 2; j++) {
        float blo = (2 * j     < K_) ? bc[2 * j]     : 0.0f;
        float bhi = (2 * j + 1 < K_) ? bc[2 * j + 1] : 0.0f;
        acc2[j] = pack2(blo, bhi);
    }

#pragma unroll 4
    for (int c = 0; c < C_; c++) {
        float v = fmb[(size_t)c * PL];
        unsigned long long v2 = pack2(v, v);
#pragma unroll
        for (int j = 0; j < 6; j++) {
            ulonglong2 w = sWT2[c][j];
            FMA2(acc2[2 * j],     v2, w.x);
            FMA2(acc2[2 * j + 1], v2, w.y);
        }
    }

    float acc[K_ + 1];
#pragma unroll
    for (int j = 0; j < (K_ + 1) / 2; j++)
        unpack2(acc2[j], acc[2 * j], acc[2 * j + 1]);

    // --- softmax over K ---
    float m = acc[0];
#pragma unroll
    for (int k = 1; k < K_; k++) m = fmaxf(m, acc[k]);
    float s = 0.f;
#pragma unroll
    for (int k = 0; k < K_; k++) { acc[k] = __expf(acc[k] - m); s += acc[k]; }
    float inv = 1.0f / s;

    // --- q partials ---
    int w = tid >> 5, l = tid & 31;
#pragma unroll
    for (int k = 0; k < K_; k++) {
        float sv = acc[k] * inv;
        float v0 = sv * xd0, v1 = sv * xd1, v2 = sv * xd2;
#pragma unroll
        for (int off = 16; off > 0; off >>= 1) {
            v0 += __shfl_down_sync(0xffffffffu, v0, off);
            v1 += __shfl_down_sync(0xffffffffu, v1, off);
            v2 += __shfl_down_sync(0xffffffffu, v2, off);
        }
        if (l == 0) {
            spart[w][k * 3 + 0] = v0;
            spart[w][k * 3 + 1] = v1;
            spart[w][k * 3 + 2] = v2;
        }
    }
    __syncthreads();
    if (tid < K_ * 3) {
        float ps = spart[0][tid] + spart[1][tid] + spart[2][tid] + spart[3][tid];
        g_part[((size_t)b * NBLK + blockIdx.x) * (K_ * 3) + tid] = ps;
    }
}

// ---------------------------------------------------------------------------
// Kernel 3: q reduce (in-block, redundant per block) + final output.
// out[b,k,Y,X] = sum_c x[b,c,Y,X] * q[b,k,c]; streaming stores.
// ---------------------------------------------------------------------------
__global__ __launch_bounds__(256) void k_out(
    const float* __restrict__ x, float* __restrict__ out)
{
    __shared__ float sq[K_ * 3];
    int b = blockIdx.y;
    if (threadIdx.x < K_ * 3) {
        const float* pp = g_part + (size_t)b * NBLK * (K_ * 3) + threadIdx.x;
        float s = 0.f;
#pragma unroll
        for (int blk = 0; blk < NBLK; blk++) s += pp[blk * (K_ * 3)];
        sq[threadIdx.x] = s * (1.0f / (float)PH);
    }
    __syncthreads();

    int p4 = blockIdx.x * blockDim.x + threadIdx.x;     // float4 index < 65536
    const float4* xb = (const float4*)(x + (size_t)b * 3 * PH);
    float4 x0 = xb[p4];
    float4 x1 = xb[(PH / 4) + p4];
    float4 x2 = xb[(PH / 2) + p4];

    float4* ob = (float4*)(out + (size_t)b * K_ * PH);
#pragma unroll
    for (int k = 0; k < K_; k++) {
        float w0 = sq[k * 3 + 0], w1 = sq[k * 3 + 1], w2 = sq[k * 3 + 2];
        float4 r;
        r.x = fmaf(x0.x, w0, fmaf(x1.x, w1, x2.x * w2));
        r.y = fmaf(x0.y, w0, fmaf(x1.y, w1, x2.y * w2));
        r.z = fmaf(x0.z, w0, fmaf(x1.z, w1, x2.z * w2));
        r.w = fmaf(x0.w, w0, fmaf(x1.w, w1, x2.w * w2));
        __stcs(&ob[(size_t)k * (PH / 4) + p4], r);
    }
}

// ---------------------------------------------------------------------------
extern "C" void kernel_launch(void* const* d_in, const int* in_sizes, int n_in,
                              void* d_out, int out_size)
{
    const float* fm  = (const float*)d_in[0];  // [8,256,64,64]
    const float* x   = (const float*)d_in[1];  // [8,3,512,512]
    const float* Wc  = (const float*)d_in[2];  // [21,256]
    const float* bc  = (const float*)d_in[3];  // [21]
    float* out = (float*)d_out;                // [8,21,512,512]

    k_adj_x<<<B_ * 3 * HH / 4, 256>>>(x);
    {
        dim3 grid(NBLK, B_);
        k_fused<<<grid, 128>>>(fm, Wc, bc);
    }
    {
        dim3 grid((PH / 4) / 256, B_);
        k_out<<<grid, 256>>>(x, out);
    }
}

// round 7
// speedup vs baseline: 1.0206x; 1.0206x over previous
#include <cuda_runtime.h>
#include <cuda_bf16.h>

// Problem constants
#define B_  8
#define C_  256
#define K_  21
#define KP  24            // K padded to 12 f32x2 pairs
#define HL  64
#define PL  (HL*HL)       // 4096 low-res pixels
#define HH  512
#define PH  (HH*HH)       // 262144 hi-res pixels
#define NBLK 32           // q-partial blocks per batch
#define NT  20            // taps per low-res bin (padded with zeros)
#define RUP (511.0f/63.0f)
#define SDN (63.0f/511.0f)

// Scratch (device globals)
__device__ float g_tmpx[B_ * 3 * HH * HL];       // X-pass adjoint (3 MB)
__device__ float g_part[B_ * NBLK * K_ * 3];     // q block partials

// packed f32x2 helpers
#define FMA2(acc, v2, w2) \
    asm("fma.rn.f32x2 %0, %1, %2, %0;" : "+l"(acc) : "l"(v2), "l"(w2))
#define FMA2O(dst, a2, w2, c2) \
    asm("fma.rn.f32x2 %0, %1, %2, %3;" : "=l"(dst) : "l"(a2), "l"(w2), "l"(c2))
__device__ __forceinline__ unsigned long long pack2(float lo, float hi) {
    unsigned long long r;
    asm("mov.b64 %0, {%1, %2};" : "=l"(r) : "r"(__float_as_uint(lo)), "r"(__float_as_uint(hi)));
    return r;
}
__device__ __forceinline__ void unpack2(unsigned long long v, float& lo, float& hi) {
    unsigned int a, b;
    asm("mov.b64 {%0, %1}, %2;" : "=r"(a), "=r"(b) : "l"(v));
    lo = __uint_as_float(a); hi = __uint_as_float(b);
}

// Adjoint tap weight: contribution of hires coord X to lowres bin l (one axis).
__device__ __forceinline__ float tap_w(int X, int l) {
    if (X > HH - 1) return 0.0f;
    float xs = (float)X * SDN;
    int   x0 = (int)xs;
    float wx = xs - (float)x0;
    int   x1 = min(x0 + 1, HL - 1);
    return (x0 == l ? (1.0f - wx) : 0.0f) + (x1 == l ? wx : 0.0f);
}
// First tap index for bin l, clamped so the NT-tap window stays in [0, HH).
__device__ __forceinline__ int tap_base(int l) {
    int lo = max(0, (int)floorf((l - 1) * RUP));
    return min(lo, HH - NT);
}

// ---------------------------------------------------------------------------
// Kernel 1: adjoint of bilinear upsample, X direction, table-driven.
// swt transposed [j][xl] so warp reads are stride-1 (conflict-free).
// ---------------------------------------------------------------------------
__global__ __launch_bounds__(256) void k_adj_x(const float* __restrict__ x)
{
    __shared__ float srow[4][HH];
    __shared__ float swt[NT][HL];     // TRANSPOSED: taps j major
    __shared__ int   sbase[HL];

    int tid    = threadIdx.x;
    int sub    = tid >> 6;
    int lane64 = tid & 63;
    int rowid  = blockIdx.x * 4 + sub;         // (b*3+c)*HH + Y

    // build tap table (threads 0..63), once per block
    if (tid < HL) {
        int l = tid;
        int base = tap_base(l);
        sbase[l] = base;
#pragma unroll
        for (int j = 0; j < NT; j++) swt[j][l] = tap_w(base + j, l);
    }
    // coalesced row load: 64 threads x 2 float4 = 512 floats
    {
        float4*       s4 = (float4*)srow[sub];
        const float4* r4 = (const float4*)(x + (size_t)rowid * HH);
        s4[lane64]      = r4[lane64];
        s4[64 + lane64] = r4[64 + lane64];
    }
    __syncthreads();

    const int xl   = lane64;
    const int base = sbase[xl];
    const float* row = srow[sub] + base;
    float s = 0.f;
#pragma unroll
    for (int j = 0; j < NT; j++) s = fmaf(swt[j][xl], row[j], s);

    g_tmpx[(size_t)rowid * HL + xl] = s;
}

// ---------------------------------------------------------------------------
// Kernel 2 (fused): Y-adjoint + logits (split-C f32x2 GEMM) + softmax
//                   + q block-partials.
// grid (32, 8), block 256: tid&127 = pixel, tid>>7 = C half.
// ---------------------------------------------------------------------------
__global__ __launch_bounds__(256) void k_fused(
    const float* __restrict__ fm, const float* __restrict__ Wc,
    const float* __restrict__ bc)
{
    __shared__ ulonglong2 sWT2[C_][6];            // W^T padded (24.6 KB)
    __shared__ unsigned long long sacc[128][KP/2];// upper-half partials (12.3 KB)
    __shared__ float      spart[4][K_ * 3];
    __shared__ float      sywt[2][NT];

    int tid  = threadIdx.x;
    int px   = tid & 127;
    int half = tid >> 7;                  // 0 or 1
    int b    = blockIdx.y;
    int p    = blockIdx.x * 128 + px;
    int xl   = p & (HL - 1);
    int yl   = p >> 6;
    int yl0  = (blockIdx.x * 128) >> 6;

    // fill W^T (padded zeros for k >= 21); float view of sWT2 is [C_][KP]
    {
        float* sWTf = (float*)sWT2;
        for (int i = tid; i < C_ * KP; i += 256) {
            int c = i / KP, k = i % KP;
            sWTf[i] = (k < K_) ? Wc[k * C_ + c] : 0.0f;
        }
    }
    if (tid < 2 * NT) {
        int r = tid / NT, j = tid % NT;
        int l = yl0 + r;
        sywt[r][j] = tap_w(tap_base(l) + j, l);
    }
    __syncthreads();

    // --- Y-adjoint gather (lower half only) ---
    float xd0 = 0.f, xd1 = 0.f, xd2 = 0.f;
    if (half == 0) {
        int base = tap_base(yl);
        const float* wrow = sywt[yl - yl0];
        const float* t0 = g_tmpx + ((size_t)(b * 3 + 0) * HH + base) * HL + xl;
        const float* t1 = g_tmpx + ((size_t)(b * 3 + 1) * HH + base) * HL + xl;
        const float* t2 = g_tmpx + ((size_t)(b * 3 + 2) * HH + base) * HL + xl;
#pragma unroll
        for (int j = 0; j < NT; j++) {
            float w = wrow[j];
            size_t o = (size_t)j * HL;
            xd0 = fmaf(w, t0[o], xd0);
            xd1 = fmaf(w, t1[o], xd1);
            xd2 = fmaf(w, t2[o], xd2);
        }
    }

    // --- logits GEMM, split C: this thread does c in [half*128, half*128+128) ---
    const float* fmb = fm + (size_t)b * C_ * PL + (size_t)half * 128 * PL + p;
    unsigned long long acc2[KP / 2];
#pragma unroll
    for (int j = 0; j < KP / 2; j++) {
        float blo = (half == 0 && 2 * j     < K_) ? bc[2 * j]     : 0.0f;
        float bhi = (half == 0 && 2 * j + 1 < K_) ? bc[2 * j + 1] : 0.0f;
        acc2[j] = pack2(blo, bhi);
    }

    const ulonglong2 (*wrow2)[6] = sWT2 + half * 128;
#pragma unroll 4
    for (int c = 0; c < 128; c++) {
        float v = fmb[(size_t)c * PL];
        unsigned long long v2 = pack2(v, v);
#pragma unroll
        for (int j = 0; j < 6; j++) {
            ulonglong2 w = wrow2[c][j];
            FMA2(acc2[2 * j],     v2, w.x);
            FMA2(acc2[2 * j + 1], v2, w.y);
        }
    }

    // combine halves
    if (half == 1) {
#pragma unroll
        for (int j = 0; j < KP / 2; j++) sacc[px][j] = acc2[j];
    }
    __syncthreads();
    if (half == 1) return;

    float acc[K_ + 1];
#pragma unroll
    for (int j = 0; j < (K_ + 1) / 2; j++) {
        float lo, hi, lo2, hi2;
        unpack2(acc2[j], lo, hi);
        unpack2(sacc[px][j], lo2, hi2);
        acc[2 * j] = lo + lo2; acc[2 * j + 1] = hi + hi2;
    }

    // --- softmax over K ---
    float m = acc[0];
#pragma unroll
    for (int k = 1; k < K_; k++) m = fmaxf(m, acc[k]);
    float s = 0.f;
#pragma unroll
    for (int k = 0; k < K_; k++) { acc[k] = __expf(acc[k] - m); s += acc[k]; }
    float inv = 1.0f / s;

    // --- q partials ---
    int w = px >> 5, l = px & 31;
#pragma unroll
    for (int k = 0; k < K_; k++) {
        float sv = acc[k] * inv;
        float v0 = sv * xd0, v1 = sv * xd1, v2 = sv * xd2;
#pragma unroll
        for (int off = 16; off > 0; off >>= 1) {
            v0 += __shfl_down_sync(0xffffffffu, v0, off);
            v1 += __shfl_down_sync(0xffffffffu, v1, off);
            v2 += __shfl_down_sync(0xffffffffu, v2, off);
        }
        if (l == 0) {
            spart[w][k * 3 + 0] = v0;
            spart[w][k * 3 + 1] = v1;
            spart[w][k * 3 + 2] = v2;
        }
    }
    __syncthreads();
    if (tid < K_ * 3) {
        float ps = spart[0][tid] + spart[1][tid] + spart[2][tid] + spart[3][tid];
        g_part[((size_t)b * NBLK + blockIdx.x) * (K_ * 3) + tid] = ps;
    }
}

// ---------------------------------------------------------------------------
// Kernel 3: q reduce + final output, f32x2 math, 8 px (2 float4) per thread.
// out[b,k,Y,X] = sum_c x[b,c,Y,X] * q[b,k,c]; streaming stores.
// grid (128, 8), block 256.
// ---------------------------------------------------------------------------
__global__ __launch_bounds__(256) void k_out(
    const float* __restrict__ x, float* __restrict__ out)
{
    __shared__ unsigned long long sq2[K_ * 3];    // q broadcast-packed (w,w)
    int b = blockIdx.y;
    if (threadIdx.x < K_ * 3) {
        const float* pp = g_part + (size_t)b * NBLK * (K_ * 3) + threadIdx.x;
        float s = 0.f;
#pragma unroll
        for (int blk = 0; blk < NBLK; blk++) s += pp[blk * (K_ * 3)];
        s *= (1.0f / (float)PH);
        sq2[threadIdx.x] = pack2(s, s);
    }
    __syncthreads();

    int t = blockIdx.x * blockDim.x + threadIdx.x;    // < 32768
    const float4* xb = (const float4*)(x + (size_t)b * 3 * PH);

    // load 2 float4 per channel; alias each float4 as 2 packed f32x2
    ulonglong2 x0a = *(const ulonglong2*)&xb[2 * t];
    ulonglong2 x0b = *(const ulonglong2*)&xb[2 * t + 1];
    ulonglong2 x1a = *(const ulonglong2*)&xb[(PH / 4) + 2 * t];
    ulonglong2 x1b = *(const ulonglong2*)&xb[(PH / 4) + 2 * t + 1];
    ulonglong2 x2a = *(const ulonglong2*)&xb[(PH / 2) + 2 * t];
    ulonglong2 x2b = *(const ulonglong2*)&xb[(PH / 2) + 2 * t + 1];

    float4* ob = (float4*)(out + (size_t)b * K_ * PH);
#pragma unroll
    for (int k = 0; k < K_; k++) {
        unsigned long long w0 = sq2[k * 3 + 0];
        unsigned long long w1 = sq2[k * 3 + 1];
        unsigned long long w2 = sq2[k * 3 + 2];
        ulonglong2 ra, rb;
        unsigned long long tmp;
        // ra = x0a*w0 + x1a*w1 + x2a*w2   (per 64-bit half)
        FMA2O(tmp,  x1a.x, w1, 0ULL);  // careful: need c operand; build chain
        FMA2O(ra.x, x2a.x, w2, tmp);
        FMA2(ra.x, x0a.x, w0);
        FMA2O(tmp,  x1a.y, w1, 0ULL);
        FMA2O(ra.y, x2a.y, w2, tmp);
        FMA2(ra.y, x0a.y, w0);
        FMA2O(tmp,  x1b.x, w1, 0ULL);
        FMA2O(rb.x, x2b.x, w2, tmp);
        FMA2(rb.x, x0b.x, w0);
        FMA2O(tmp,  x1b.y, w1, 0ULL);
        FMA2O(rb.y, x2b.y, w2, tmp);
        FMA2(rb.y, x0b.y, w0);

        float4* dst = &ob[(size_t)k * (PH / 4) + 2 * t];
        __stcs(dst,     *(float4*)&ra);
        __stcs(dst + 1, *(float4*)&rb);
    }
}

// ---------------------------------------------------------------------------
extern "C" void kernel_launch(void* const* d_in, const int* in_sizes, int n_in,
                              void* d_out, int out_size)
{
    const float* fm  = (const float*)d_in[0];  // [8,256,64,64]
    const float* x   = (const float*)d_in[1];  // [8,3,512,512]
    const float* Wc  = (const float*)d_in[2];  // [21,256]
    const float* bc  = (const float*)d_in[3];  // [21]
    float* out = (float*)d_out;                // [8,21,512,512]

    k_adj_x<<<B_ * 3 * HH / 4, 256>>>(x);
    {
        dim3 grid(NBLK, B_);
        k_fused<<<grid, 256>>>(fm, Wc, bc);
    }
    {
        dim3 grid((PH / 4 / 2) / 256, B_);
        k_out<<<grid, 256>>>(x, out);
    }
}